// round 4
// baseline (speedup 1.0000x reference)
#include <cuda_runtime.h>
#include <cstdint>

#define NN 2048
#define TT 128
#define FF 64
#define HH 128
#define GG 384   // 3*H
#define EE 32768
#define CS 8     // cluster size for the GRU

// ---------------- scratch (device globals: no allocs allowed) ----------------
__device__ float g_deg[NN];
__device__ float g_dinv[NN];
__device__ float g_xs1[NN*HH];
__device__ float g_acc1[NN*HH];
__device__ float g_h1[NN*HH];
__device__ float g_xs2[NN*HH];
__device__ float g_acc2[NN*HH];
__device__ float g_h2[NN*HH];
__device__ float g_wT[HH*GG];     // w_ih transposed: [k][g]
__device__ float g_gi[NN*GG];     // precomputed input gates (+b_ih)
__device__ float g_hist[NN*HH];   // h after each GRU step
__device__ int   g_stride;        // 1 if edge_index is int32, 2 if int64 words

// ---------------- helpers ----------------
__device__ __forceinline__ float fsig(float x) {
    return 1.0f / (1.0f + __expf(-x));
}
__device__ __forceinline__ uint32_t smem_u32(const void* p) {
    uint32_t a;
    asm("{ .reg .u64 t; cvta.to.shared.u64 t, %1; cvt.u32.u64 %0, t; }"
        : "=r"(a) : "l"(p));
    return a;
}
__device__ __forceinline__ uint32_t mapa_u32(uint32_t addr, uint32_t rank) {
    uint32_t r;
    asm("mapa.shared::cluster.u32 %0, %1, %2;" : "=r"(r) : "r"(addr), "r"(rank));
    return r;
}
__device__ __forceinline__ void st_cluster_b32(uint32_t addr, float v) {
    asm volatile("st.shared::cluster.b32 [%0], %1;"
                 :: "r"(addr), "r"(__float_as_uint(v)) : "memory");
}
__device__ __forceinline__ void mbar_arrive_cluster(uint32_t mbar) {
    asm volatile("mbarrier.arrive.release.cluster.shared::cluster.b64 _, [%0];"
                 :: "r"(mbar) : "memory");
}
__device__ __forceinline__ void mbar_init(uint32_t mbar, uint32_t cnt) {
    asm volatile("mbarrier.init.shared.b64 [%0], %1;" :: "r"(mbar), "r"(cnt) : "memory");
}
__device__ __forceinline__ void mbar_wait_cluster(uint32_t mbar, uint32_t parity) {
    uint32_t done;
    asm volatile(
        "{\n\t"
        ".reg .pred p;\n\t"
        "mbarrier.try_wait.parity.acquire.cluster.shared::cta.b64 p, [%1], %2;\n\t"
        "selp.b32 %0, 1, 0, p;\n\t"
        "}" : "=r"(done) : "r"(mbar), "r"(parity) : "memory");
    if (!done) {
        asm volatile(
            "{\n\t"
            ".reg .pred P1;\n\t"
            "WL_%=:\n\t"
            "mbarrier.try_wait.parity.acquire.cluster.shared::cta.b64 P1, [%0], %1, 0x989680;\n\t"
            "@P1 bra.uni WD_%=;\n\t"
            "bra.uni WL_%=;\n\t"
            "WD_%=:\n\t"
            "}" :: "r"(mbar), "r"(parity) : "memory");
    }
}

// ---------------- kernels ----------------

// Detect int32 vs int64 edge_index by inspecting high words (values < 2048, so
// int64 storage means every odd 32-bit word is zero).
__global__ void k_detect(const int* __restrict__ ei) {
    int any = 0;
    for (int i = threadIdx.x; i < 1024; i += 32) any |= ei[2*i + 1];
    unsigned b = __ballot_sync(0xFFFFFFFFu, any != 0);
    if (threadIdx.x == 0) g_stride = b ? 1 : 2;
}

__global__ void k_init() {
    int i = blockIdx.x * blockDim.x + threadIdx.x;
    if (i < NN*HH) { g_acc1[i] = 0.f; g_acc2[i] = 0.f; }
    if (i < NN)    g_deg[i] = 1.0f;   // self loop
}

__global__ void k_deg(const int* __restrict__ ei) {
    int e = blockIdx.x * blockDim.x + threadIdx.x;
    if (e < EE) {
        int s = g_stride;
        int d = ei[(EE + e) * s];
        atomicAdd(&g_deg[d], 1.0f);
    }
}

__global__ void k_dinv() {
    int n = blockIdx.x * blockDim.x + threadIdx.x;
    if (n < NN) g_dinv[n] = rsqrtf(g_deg[n]);
}

// xs1[n,:] = dinv[n] * (x[n,127,:] @ W1)
__global__ void k_xs1(const float* __restrict__ x, const float* __restrict__ W1) {
    __shared__ float xr[FF];
    int n = blockIdx.x, t = threadIdx.x;
    if (t < FF) xr[t] = x[n*(TT*FF) + 127*FF + t];
    __syncthreads();
    float a = 0.f;
    #pragma unroll
    for (int k = 0; k < FF; k++) a = fmaf(xr[k], W1[k*HH + t], a);
    g_xs1[n*HH + t] = a * g_dinv[n];
}

__global__ void k_scat1(const int* __restrict__ ei) {
    int t = threadIdx.x;
    int e = blockIdx.x * 4 + (t >> 7);
    int j = t & 127;
    int s = g_stride;
    int sr = ei[e * s], d = ei[(EE + e) * s];
    atomicAdd(&g_acc1[d*HH + j], g_xs1[sr*HH + j]);
}

__global__ void k_fin1(const float* __restrict__ b1) {
    int i = blockIdx.x * blockDim.x + threadIdx.x;
    if (i < NN*HH) {
        int n = i >> 7;
        g_h1[i] = g_dinv[n] * (g_acc1[i] + g_xs1[i]) + b1[i & 127];
    }
}

__global__ void k_xs2(const float* __restrict__ W2) {
    __shared__ float hr[HH];
    int n = blockIdx.x, t = threadIdx.x;
    hr[t] = g_h1[n*HH + t];
    __syncthreads();
    float a = 0.f;
    #pragma unroll
    for (int k = 0; k < HH; k++) a = fmaf(hr[k], W2[k*HH + t], a);
    g_xs2[n*HH + t] = a * g_dinv[n];
}

__global__ void k_scat2(const int* __restrict__ ei) {
    int t = threadIdx.x;
    int e = blockIdx.x * 4 + (t >> 7);
    int j = t & 127;
    int s = g_stride;
    int sr = ei[e * s], d = ei[(EE + e) * s];
    atomicAdd(&g_acc2[d*HH + j], g_xs2[sr*HH + j]);
}

__global__ void k_fin2(const float* __restrict__ b2) {
    int i = blockIdx.x * blockDim.x + threadIdx.x;
    if (i < NN*HH) {
        int n = i >> 7;
        g_h2[i] = g_dinv[n] * (g_acc2[i] + g_xs2[i]) + b2[i & 127];
    }
}

__global__ void k_wT(const float* __restrict__ wih) {
    int i = blockIdx.x * blockDim.x + threadIdx.x;
    if (i < GG*HH) { int g = i >> 7, k = i & 127; g_wT[k*GG + g] = wih[i]; }
}

// GI[n,g] = h2[n,:] . w_ih[g,:] + b_ih[g]   (16 rows per block)
__global__ void k_gi(const float* __restrict__ bih) {
    __shared__ float hs[16][HH];
    int g = threadIdx.x;
    int n0 = blockIdx.x * 16;
    for (int i = g; i < 16*HH; i += GG) hs[i >> 7][i & 127] = g_h2[n0*HH + i];
    __syncthreads();
    float acc[16];
    #pragma unroll
    for (int i = 0; i < 16; i++) acc[i] = 0.f;
    for (int k = 0; k < HH; k++) {
        float w = g_wT[k*GG + g];
        #pragma unroll
        for (int i = 0; i < 16; i++) acc[i] = fmaf(hs[i][k], w, acc[i]);
    }
    float b = bih[g];
    #pragma unroll
    for (int i = 0; i < 16; i++) g_gi[(n0 + i)*GG + g] = acc[i] + b;
}

// ---------------------------------------------------------------------------
// Sequential GRU over n=0..2047, hidden = one [128] vector, spread over an
// 8-CTA cluster (8 SMs). CTA c owns hidden units j in [16c, 16c+16):
//   warps 0-2 (gate = wid): lane -> (jj = lane>>1, kh = lane&1) computes the
//     half-dot (64 MACs) of w_hh row gate*128 + 16c + jj over k in [64kh,64kh+64),
//     weights in registers. shfl-combine -> ssum.
//   warp 3: gate nonlinearities for the 16 owned j, then broadcasts the new h
//     values to all 8 CTAs' hbuf via mapa + st.shared::cluster, signalled by
//     mbarrier.arrive.release.cluster (count 128 = 8 CTAs x 16 lanes).
// Double-buffered hbuf/mbar; max inter-CTA skew is 1 step, so 2 buffers are
// race-free: CTA A's write to buffer b at end of step n is causally behind
// every CTA B's last read of b (read -> B sync -> B arrive -> A wait -> A write).
// ---------------------------------------------------------------------------
__global__ __launch_bounds__(128, 1) __cluster_dims__(CS, 1, 1)
void k_gru(const float* __restrict__ whh, const float* __restrict__ bhh) {
    __shared__ __align__(16) float hbuf[2][HH];
    __shared__ float ssum[2][48];
    __shared__ __align__(8) unsigned long long mbar[2];

    uint32_t rank;
    asm("mov.u32 %0, %%cluster_ctarank;" : "=r"(rank));
    int tid = threadIdx.x;
    int wid = tid >> 5, lane = tid & 31;
    int Jb = (int)rank * 16;

    uint32_t hb_u32 = smem_u32(&hbuf[0][0]);
    uint32_t mb_u32 = smem_u32(&mbar[0]);

    if (tid == 0) { mbar_init(mb_u32, 128); mbar_init(mb_u32 + 8, 128); }
    if (tid < HH) hbuf[0][tid] = 0.f;
    __syncthreads();
    asm volatile("barrier.cluster.arrive.aligned;" ::: "memory");
    asm volatile("barrier.cluster.wait.aligned;" ::: "memory");

    // ---- role-specific persistent state ----
    // workers (wid<3)
    int gate = wid, jj = lane >> 1, kh = lane & 1;
    float4 w[16];
    if (wid < 3) {
        const float4* wp = (const float4*)(whh + (size_t)(gate*HH + Jb + jj)*HH + kh*64);
        #pragma unroll
        for (int t = 0; t < 16; t++) w[t] = wp[t];
    }
    // warp 3
    int j = lane & 15;
    bool act = (wid == 3) && (lane < 16);
    float bhr = 0.f, bhz = 0.f, bhn = 0.f, hj = 0.f;
    float gr = 0.f, gz = 0.f, gn = 0.f;
    uint32_t t0 = 0, t1 = 0, t2 = 0, t3 = 0;   // remote hbuf bases (4 targets)
    uint32_t m0 = 0, m1 = 0, m2 = 0, m3 = 0;   // remote mbar bases
    if (wid == 3) {
        if (act) {
            bhr = bhh[Jb + j]; bhz = bhh[HH + Jb + j]; bhn = bhh[2*HH + Jb + j];
            gr = g_gi[Jb + j]; gz = g_gi[HH + Jb + j]; gn = g_gi[2*HH + Jb + j];
        }
        uint32_t c0 = (lane < 16) ? 0u : 4u;
        t0 = mapa_u32(hb_u32, c0);     m0 = mapa_u32(mb_u32, c0);
        t1 = mapa_u32(hb_u32, c0 + 1); m1 = mapa_u32(mb_u32, c0 + 1);
        t2 = mapa_u32(hb_u32, c0 + 2); m2 = mapa_u32(mb_u32, c0 + 2);
        t3 = mapa_u32(hb_u32, c0 + 3); m3 = mapa_u32(mb_u32, c0 + 3);
    }

    int ph0 = 0, ph1 = 0;
    for (int n = 0; n < NN; n++) {
        int p = n & 1;
        if (wid < 3) {
            if (n > 0) {
                if (p == 0) { mbar_wait_cluster(mb_u32, ph0); ph0 ^= 1; }
                else        { mbar_wait_cluster(mb_u32 + 8, ph1); ph1 ^= 1; }
            }
            const float4* hp = (const float4*)(&hbuf[p][kh * 64]);
            float a0 = 0.f, a1 = 0.f, a2 = 0.f, a3 = 0.f;
            #pragma unroll
            for (int t = 0; t < 16; t++) {
                float4 hv = hp[t];
                a0 = fmaf(w[t].x, hv.x, a0);
                a1 = fmaf(w[t].y, hv.y, a1);
                a2 = fmaf(w[t].z, hv.z, a2);
                a3 = fmaf(w[t].w, hv.w, a3);
            }
            float s = (a0 + a1) + (a2 + a3);
            s += __shfl_xor_sync(0xFFFFFFFFu, s, 1);
            if (kh == 0) ssum[p][gate * 16 + jj] = s;
        }
        __syncthreads();
        if (wid == 3) {
            if (act) {
                float sr = ssum[p][j], sz = ssum[p][16 + j], sn = ssum[p][32 + j];
                float r  = fsig(gr + sr + bhr);
                float z  = fsig(gz + sz + bhz);
                float ta = gn + r * (sn + bhn);
                float nv = 2.0f * fsig(2.0f * ta) - 1.0f;   // tanh
                hj = (1.0f - z) * nv + z * hj;
            }
            // critical path first: broadcast new h + arrive on all CTAs
            float hbv = __shfl_sync(0xFFFFFFFFu, hj, lane & 15);
            if (n < NN - 1) {
                int pn = p ^ 1;
                uint32_t off = (uint32_t)(pn * HH + Jb + (lane & 15)) * 4u;
                st_cluster_b32(t0 + off, hbv);
                st_cluster_b32(t1 + off, hbv);
                st_cluster_b32(t2 + off, hbv);
                st_cluster_b32(t3 + off, hbv);
                uint32_t mo = (uint32_t)(pn * 8);
                mbar_arrive_cluster(m0 + mo);
                mbar_arrive_cluster(m1 + mo);
                mbar_arrive_cluster(m2 + mo);
                mbar_arrive_cluster(m3 + mo);
            }
            // off the critical path: history store + next-step gi prefetch
            if (act) {
                g_hist[(size_t)n * HH + Jb + j] = hj;
                if (n + 1 < NN) {
                    size_t b = (size_t)(n + 1) * GG + Jb + j;
                    gr = g_gi[b]; gz = g_gi[b + HH]; gn = g_gi[b + 2*HH];
                }
            }
        }
    }
}

// out[n] = hist[n,:] . fc_w + fc_b  (one warp per n)
__global__ void k_out(const float* __restrict__ fcw, const float* __restrict__ fcb,
                      float* __restrict__ out) {
    int w = threadIdx.x >> 5, lane = threadIdx.x & 31;
    int n = blockIdx.x * 8 + w;
    const float4* hp = (const float4*)(g_hist + (size_t)n*HH);
    const float4* wp = (const float4*)fcw;
    float4 h = hp[lane], ww = wp[lane];
    float s = h.x*ww.x + h.y*ww.y + h.z*ww.z + h.w*ww.w;
    s += __shfl_xor_sync(0xFFFFFFFFu, s, 16);
    s += __shfl_xor_sync(0xFFFFFFFFu, s, 8);
    s += __shfl_xor_sync(0xFFFFFFFFu, s, 4);
    s += __shfl_xor_sync(0xFFFFFFFFu, s, 2);
    s += __shfl_xor_sync(0xFFFFFFFFu, s, 1);
    if (lane == 0) out[n] = s + fcb[0];
}

// ---------------- launch ----------------
extern "C" void kernel_launch(void* const* d_in, const int* in_sizes, int n_in,
                              void* d_out, int out_size) {
    const float* x   = (const float*)d_in[0];
    const int*   ei  = (const int*)  d_in[1];
    const float* W1  = (const float*)d_in[2];
    const float* b1  = (const float*)d_in[3];
    const float* W2  = (const float*)d_in[4];
    const float* b2  = (const float*)d_in[5];
    const float* wih = (const float*)d_in[6];
    const float* whh = (const float*)d_in[7];
    const float* bih = (const float*)d_in[8];
    const float* bhh = (const float*)d_in[9];
    const float* fcw = (const float*)d_in[10];
    const float* fcb = (const float*)d_in[11];
    float* out = (float*)d_out;

    k_detect<<<1, 32>>>(ei);
    k_init<<<(NN*HH + 255)/256, 256>>>();
    k_deg<<<EE/256, 256>>>(ei);
    k_dinv<<<(NN + 255)/256, 256>>>();
    k_xs1<<<NN, HH>>>(x, W1);
    k_scat1<<<EE/4, 512>>>(ei);
    k_fin1<<<NN*HH/256, 256>>>(b1);
    k_xs2<<<NN, HH>>>(W2);
    k_scat2<<<EE/4, 512>>>(ei);
    k_fin2<<<NN*HH/256, 256>>>(b2);
    k_wT<<<GG*HH/256, 256>>>(wih);
    k_gi<<<NN/16, GG>>>(bih);
    k_gru<<<CS, 128>>>(whh, bhh);
    k_out<<<NN/8, 256>>>(fcw, fcb, out);
}

// round 5
// speedup vs baseline: 2.0512x; 2.0512x over previous
#include <cuda_runtime.h>
#include <cstdint>

#define NN 2048
#define TT 128
#define FF 64
#define HH 128
#define GG 384   // 3*H
#define EE 32768

// ---------------- scratch (device globals: no allocs allowed) ----------------
__device__ float g_deg[NN];
__device__ float g_dinv[NN];
__device__ float g_xs1[NN*HH];
__device__ float g_acc1[NN*HH];
__device__ float g_xs2[NN*HH];
__device__ float g_acc2[NN*HH];
__device__ float g_wT[HH*GG];     // w_ih transposed: [k][g]
__device__ float g_gi[NN*GG];     // precomputed input gates (+b_ih)
__device__ float g_hist[NN*HH];   // h after each GRU step
__device__ int   g_stride;        // 1 if edge_index is int32, 2 if int64 words

// ---------------- helpers ----------------
__device__ __forceinline__ unsigned long long ffma2(unsigned long long a,
                                                    unsigned long long b,
                                                    unsigned long long c) {
    asm("fma.rn.f32x2 %0, %1, %2, %0;" : "+l"(c) : "l"(a), "l"(b));
    return c;
}
__device__ __forceinline__ float2 unpack2(unsigned long long v) {
    float2 r; asm("mov.b64 {%0,%1}, %2;" : "=f"(r.x), "=f"(r.y) : "l"(v)); return r;
}
__device__ __forceinline__ float fsig(float x) {
    return 1.0f / (1.0f + __expf(-x));
}

// ---------------- kernels ----------------

// Detect int32 vs int64 edge_index by inspecting high words (values < 2048, so
// int64 storage means every odd 32-bit word is zero).
__global__ void k_detect(const int* __restrict__ ei) {
    int any = 0;
    for (int i = threadIdx.x; i < 1024; i += 32) any |= ei[2*i + 1];
    unsigned b = __ballot_sync(0xFFFFFFFFu, any != 0);
    if (threadIdx.x == 0) g_stride = b ? 1 : 2;
}

__global__ void k_init() {
    int i = blockIdx.x * blockDim.x + threadIdx.x;
    if (i < NN*HH) { g_acc1[i] = 0.f; g_acc2[i] = 0.f; }
    if (i < NN)    g_deg[i] = 1.0f;   // self loop
}

__global__ void k_deg(const int* __restrict__ ei) {
    int e = blockIdx.x * blockDim.x + threadIdx.x;
    if (e < EE) {
        int s = g_stride;
        int d = ei[(EE + e) * s];
        atomicAdd(&g_deg[d], 1.0f);
    }
}

__global__ void k_dinv() {
    int n = blockIdx.x * blockDim.x + threadIdx.x;
    if (n < NN) g_dinv[n] = rsqrtf(g_deg[n]);
}

// xs1[n,:] = dinv[n] * (x[n,127,:] @ W1)
__global__ void k_xs1(const float* __restrict__ x, const float* __restrict__ W1) {
    __shared__ float xr[FF];
    int n = blockIdx.x, t = threadIdx.x;
    if (t < FF) xr[t] = x[n*(TT*FF) + 127*FF + t];
    __syncthreads();
    float a = 0.f;
    #pragma unroll
    for (int k = 0; k < FF; k++) a = fmaf(xr[k], W1[k*HH + t], a);
    g_xs1[n*HH + t] = a * g_dinv[n];
}

__global__ void k_scat1(const int* __restrict__ ei) {
    int t = threadIdx.x;
    int e = blockIdx.x * 4 + (t >> 7);
    int j = t & 127;
    int s = g_stride;
    int sr = ei[e * s], d = ei[(EE + e) * s];
    atomicAdd(&g_acc1[d*HH + j], g_xs1[sr*HH + j]);
}

// h1 row computed inline (fin1 fused); xs2[n,:] = dinv[n] * (h1[n,:] @ W2)
__global__ void k_xs2(const float* __restrict__ W2, const float* __restrict__ b1) {
    __shared__ float hr[HH];
    int n = blockIdx.x, t = threadIdx.x;
    float d = g_dinv[n];
    hr[t] = d * (g_acc1[n*HH + t] + g_xs1[n*HH + t]) + b1[t];
    __syncthreads();
    float a = 0.f;
    #pragma unroll
    for (int k = 0; k < HH; k++) a = fmaf(hr[k], W2[k*HH + t], a);
    g_xs2[n*HH + t] = a * d;
}

__global__ void k_scat2(const int* __restrict__ ei) {
    int t = threadIdx.x;
    int e = blockIdx.x * 4 + (t >> 7);
    int j = t & 127;
    int s = g_stride;
    int sr = ei[e * s], d = ei[(EE + e) * s];
    atomicAdd(&g_acc2[d*HH + j], g_xs2[sr*HH + j]);
}

__global__ void k_wT(const float* __restrict__ wih) {
    int i = blockIdx.x * blockDim.x + threadIdx.x;
    if (i < GG*HH) { int g = i >> 7, k = i & 127; g_wT[k*GG + g] = wih[i]; }
}

// GI[n,g] = h2[n,:] . w_ih[g,:] + b_ih[g]   (16 rows per block; h2 computed
// inline from acc2/xs2 — fin2 fused)
__global__ void k_gi(const float* __restrict__ bih, const float* __restrict__ b2) {
    __shared__ float hs[16][HH];
    int g = threadIdx.x;
    int n0 = blockIdx.x * 16;
    for (int i = g; i < 16*HH; i += GG) {
        int r = i >> 7, k = i & 127;
        hs[r][k] = g_dinv[n0 + r] * (g_acc2[n0*HH + i] + g_xs2[n0*HH + i]) + b2[k];
    }
    __syncthreads();
    float acc[16];
    #pragma unroll
    for (int i = 0; i < 16; i++) acc[i] = 0.f;
    for (int k = 0; k < HH; k++) {
        float w = g_wT[k*GG + g];
        #pragma unroll
        for (int i = 0; i < 16; i++) acc[i] = fmaf(hs[i][k], w, acc[i]);
    }
    float b = bih[g];
    #pragma unroll
    for (int i = 0; i < 16; i++) g_gi[(n0 + i)*GG + g] = acc[i] + b;
}

// ---------------------------------------------------------------------------
// Sequential GRU over n=0..2047 on ONE SM. 384 threads; thread tid owns w_hh
// row tid (gate = tid>>7, j = tid&127), weights in registers as 64 f32x2.
// Per step: FMA (floor 384 cyc with f32x2) -> STS partial sum -> bar ->
// gate threads (tid<128) run nonlinearities from register-resident gi (double
// buffered; the LDG for step n+1 issues BEFORE the FMA so its latency hides)
// -> STS new h -> bar.
// ---------------------------------------------------------------------------
__global__ __launch_bounds__(GG, 1) void k_gru(const float* __restrict__ whh,
                                               const float* __restrict__ bhh) {
    __shared__ __align__(16) float hbuf[2][HH];
    __shared__ float ssum[GG];

    int tid = threadIdx.x;
    bool isgate = (tid < HH);

    // weight row -> 64 packed f32x2 registers
    unsigned long long w[64];
    {
        const ulonglong2* wp = (const ulonglong2*)(whh + (size_t)tid * HH);
        #pragma unroll
        for (int t = 0; t < 32; t++) {
            ulonglong2 v = wp[t];
            w[2*t] = v.x; w[2*t + 1] = v.y;
        }
    }

    float bhr = 0.f, bhz = 0.f, bhn = 0.f, hj = 0.f;
    float gr = 0.f, gz = 0.f, gn = 0.f;
    if (isgate) {
        bhr = bhh[tid]; bhz = bhh[HH + tid]; bhn = bhh[2*HH + tid];
        gr = g_gi[tid]; gz = g_gi[HH + tid]; gn = g_gi[2*HH + tid];
    }

    if (isgate) { hbuf[0][tid] = 0.f; hbuf[1][tid] = 0.f; }
    __syncthreads();

    for (int n = 0; n < NN; n++) {
        int p = n & 1;
        // issue next step's gi loads early; latency hides under FMA + barrier
        float pr = 0.f, pz = 0.f, pn_ = 0.f;
        if (isgate && n + 1 < NN) {
            const float* gp = g_gi + (size_t)(n + 1) * GG + tid;
            pr = __ldg(gp); pz = __ldg(gp + HH); pn_ = __ldg(gp + 2*HH);
        }

        // 64 packed FMAs over 4 interleaved accumulators
        const ulonglong2* hp = (const ulonglong2*)(&hbuf[p][0]);
        unsigned long long a0 = 0ull, a1 = 0ull, a2 = 0ull, a3 = 0ull;
        #pragma unroll
        for (int t = 0; t < 32; t += 2) {
            ulonglong2 h0 = hp[t];
            ulonglong2 h1 = hp[t + 1];
            a0 = ffma2(w[2*t],     h0.x, a0);
            a1 = ffma2(w[2*t + 1], h0.y, a1);
            a2 = ffma2(w[2*t + 2], h1.x, a2);
            a3 = ffma2(w[2*t + 3], h1.y, a3);
        }
        float2 f0 = unpack2(a0), f1 = unpack2(a1), f2 = unpack2(a2), f3 = unpack2(a3);
        ssum[tid] = (f0.x + f0.y) + (f1.x + f1.y) + (f2.x + f2.y) + (f3.x + f3.y);
        __syncthreads();

        if (isgate) {
            float sr = ssum[tid], sz = ssum[HH + tid], sn = ssum[2*HH + tid];
            float r  = fsig(gr + sr + bhr);
            float z  = fsig(gz + sz + bhz);
            float ta = gn + r * (sn + bhn);
            float nv = 2.0f * fsig(2.0f * ta) - 1.0f;     // tanh
            hj = (1.0f - z) * nv + z * hj;
            hbuf[p ^ 1][tid] = hj;                        // critical STS first
            g_hist[(size_t)n * HH + tid] = hj;            // off critical path
            gr = pr; gz = pz; gn = pn_;
        }
        __syncthreads();
    }
}

// out[n] = hist[n,:] . fc_w + fc_b  (one warp per n)
__global__ void k_out(const float* __restrict__ fcw, const float* __restrict__ fcb,
                      float* __restrict__ out) {
    int w = threadIdx.x >> 5, lane = threadIdx.x & 31;
    int n = blockIdx.x * 8 + w;
    const float4* hp = (const float4*)(g_hist + (size_t)n*HH);
    const float4* wp = (const float4*)fcw;
    float4 h = hp[lane], ww = wp[lane];
    float s = h.x*ww.x + h.y*ww.y + h.z*ww.z + h.w*ww.w;
    s += __shfl_xor_sync(0xFFFFFFFFu, s, 16);
    s += __shfl_xor_sync(0xFFFFFFFFu, s, 8);
    s += __shfl_xor_sync(0xFFFFFFFFu, s, 4);
    s += __shfl_xor_sync(0xFFFFFFFFu, s, 2);
    s += __shfl_xor_sync(0xFFFFFFFFu, s, 1);
    if (lane == 0) out[n] = s + fcb[0];
}

// ---------------- launch ----------------
extern "C" void kernel_launch(void* const* d_in, const int* in_sizes, int n_in,
                              void* d_out, int out_size) {
    const float* x   = (const float*)d_in[0];
    const int*   ei  = (const int*)  d_in[1];
    const float* W1  = (const float*)d_in[2];
    const float* b1  = (const float*)d_in[3];
    const float* W2  = (const float*)d_in[4];
    const float* b2  = (const float*)d_in[5];
    const float* wih = (const float*)d_in[6];
    const float* whh = (const float*)d_in[7];
    const float* bih = (const float*)d_in[8];
    const float* bhh = (const float*)d_in[9];
    const float* fcw = (const float*)d_in[10];
    const float* fcb = (const float*)d_in[11];
    float* out = (float*)d_out;

    k_detect<<<1, 32>>>(ei);
    k_init<<<(NN*HH + 255)/256, 256>>>();
    k_deg<<<EE/256, 256>>>(ei);
    k_dinv<<<(NN + 255)/256, 256>>>();
    k_xs1<<<NN, HH>>>(x, W1);
    k_scat1<<<EE/4, 512>>>(ei);
    k_xs2<<<NN, HH>>>(W2, b1);
    k_scat2<<<EE/4, 512>>>(ei);
    k_wT<<<GG*HH/256, 256>>>(wih);
    k_gi<<<NN/16, GG>>>(bih, b2);
    k_gru<<<1, GG>>>(whh, bhh);
    k_out<<<NN/8, 256>>>(fcw, fcb, out);
}

// round 6
// speedup vs baseline: 2.4828x; 1.2104x over previous
#include <cuda_runtime.h>
#include <cuda_fp16.h>
#include <cstdint>

#define NN 2048
#define TT 128
#define FF 64
#define HH 128
#define GG 384   // 3*H
#define EE 32768

// ---------------- scratch (device globals: no allocs allowed) ----------------
__device__ float g_deg[NN];
__device__ float g_dinv[NN];
__device__ float g_xs1[NN*HH];
__device__ float g_acc1[NN*HH];
__device__ float g_xs2[NN*HH];
__device__ float g_acc2[NN*HH];
__device__ float g_wT[HH*GG];     // w_ih transposed: [k][g]
__device__ float g_gi[NN*GG];     // precomputed input gates (+b_ih)
__device__ float g_hist[NN*HH];   // h after each GRU step
__device__ __half g_whh16[GG*HH]; // w_hh rounded to fp16 (for tensor-core matvec)
__device__ int   g_stride;        // 1 if edge_index is int32, 2 if int64 words

// ---------------- helpers ----------------
__device__ __forceinline__ float fsig(float x) {
    return 1.0f / (1.0f + __expf(-x));
}
__device__ __forceinline__ void mma16816(float& d0, float& d1, float& d2, float& d3,
                                         uint32_t a0, uint32_t a1, uint32_t a2, uint32_t a3,
                                         uint32_t b0, uint32_t b1) {
    asm volatile(
        "mma.sync.aligned.m16n8k16.row.col.f32.f16.f16.f32 "
        "{%0,%1,%2,%3}, {%4,%5,%6,%7}, {%8,%9}, {%0,%1,%2,%3};"
        : "+f"(d0), "+f"(d1), "+f"(d2), "+f"(d3)
        : "r"(a0), "r"(a1), "r"(a2), "r"(a3), "r"(b0), "r"(b1));
}

// ---------------- kernels ----------------

// Detect int32 vs int64 edge_index by inspecting high words (values < 2048, so
// int64 storage means every odd 32-bit word is zero).
__global__ void k_detect(const int* __restrict__ ei) {
    int any = 0;
    for (int i = threadIdx.x; i < 1024; i += 32) any |= ei[2*i + 1];
    unsigned b = __ballot_sync(0xFFFFFFFFu, any != 0);
    if (threadIdx.x == 0) g_stride = b ? 1 : 2;
}

__global__ void k_init() {
    int i = blockIdx.x * blockDim.x + threadIdx.x;
    if (i < NN*HH) { g_acc1[i] = 0.f; g_acc2[i] = 0.f; }
    if (i < NN)    g_deg[i] = 1.0f;   // self loop
}

__global__ void k_deg(const int* __restrict__ ei) {
    int e = blockIdx.x * blockDim.x + threadIdx.x;
    if (e < EE) {
        int s = g_stride;
        int d = ei[(EE + e) * s];
        atomicAdd(&g_deg[d], 1.0f);
    }
}

__global__ void k_dinv() {
    int n = blockIdx.x * blockDim.x + threadIdx.x;
    if (n < NN) g_dinv[n] = rsqrtf(g_deg[n]);
}

// xs1[n,:] = dinv[n] * (x[n,127,:] @ W1)
__global__ void k_xs1(const float* __restrict__ x, const float* __restrict__ W1) {
    __shared__ float xr[FF];
    int n = blockIdx.x, t = threadIdx.x;
    if (t < FF) xr[t] = x[n*(TT*FF) + 127*FF + t];
    __syncthreads();
    float a = 0.f;
    #pragma unroll
    for (int k = 0; k < FF; k++) a = fmaf(xr[k], W1[k*HH + t], a);
    g_xs1[n*HH + t] = a * g_dinv[n];
}

__global__ void k_scat1(const int* __restrict__ ei) {
    int t = threadIdx.x;
    int e = blockIdx.x * 4 + (t >> 7);
    int j = t & 127;
    int s = g_stride;
    int sr = ei[e * s], d = ei[(EE + e) * s];
    atomicAdd(&g_acc1[d*HH + j], g_xs1[sr*HH + j]);
}

// h1 row computed inline (fin1 fused); xs2[n,:] = dinv[n] * (h1[n,:] @ W2)
__global__ void k_xs2(const float* __restrict__ W2, const float* __restrict__ b1) {
    __shared__ float hr[HH];
    int n = blockIdx.x, t = threadIdx.x;
    float d = g_dinv[n];
    hr[t] = d * (g_acc1[n*HH + t] + g_xs1[n*HH + t]) + b1[t];
    __syncthreads();
    float a = 0.f;
    #pragma unroll
    for (int k = 0; k < HH; k++) a = fmaf(hr[k], W2[k*HH + t], a);
    g_xs2[n*HH + t] = a * d;
}

__global__ void k_scat2(const int* __restrict__ ei) {
    int t = threadIdx.x;
    int e = blockIdx.x * 4 + (t >> 7);
    int j = t & 127;
    int s = g_stride;
    int sr = ei[e * s], d = ei[(EE + e) * s];
    atomicAdd(&g_acc2[d*HH + j], g_xs2[sr*HH + j]);
}

__global__ void k_wT(const float* __restrict__ wih) {
    int i = blockIdx.x * blockDim.x + threadIdx.x;
    if (i < GG*HH) { int g = i >> 7, k = i & 127; g_wT[k*GG + g] = wih[i]; }
}

__global__ void k_w16(const float* __restrict__ whh) {
    int i = blockIdx.x * blockDim.x + threadIdx.x;
    if (i < GG*HH) g_whh16[i] = __float2half_rn(whh[i]);
}

// GI[n,g] = h2[n,:] . w_ih[g,:] + b_ih[g]   (16 rows per block; h2 computed
// inline from acc2/xs2 — fin2 fused)
__global__ void k_gi(const float* __restrict__ bih, const float* __restrict__ b2) {
    __shared__ float hs[16][HH];
    int g = threadIdx.x;
    int n0 = blockIdx.x * 16;
    for (int i = g; i < 16*HH; i += GG) {
        int r = i >> 7, k = i & 127;
        hs[r][k] = g_dinv[n0 + r] * (g_acc2[n0*HH + i] + g_xs2[n0*HH + i]) + b2[k];
    }
    __syncthreads();
    float acc[16];
    #pragma unroll
    for (int i = 0; i < 16; i++) acc[i] = 0.f;
    for (int k = 0; k < HH; k++) {
        float w = g_wT[k*GG + g];
        #pragma unroll
        for (int i = 0; i < 16; i++) acc[i] = fmaf(hs[i][k], w, acc[i]);
    }
    float b = bih[g];
    #pragma unroll
    for (int i = 0; i < 16; i++) g_gi[(n0 + i)*GG + g] = acc[i] + b;
}

// ---------------------------------------------------------------------------
// Sequential GRU on ONE SM using the tensor core for the recurrent matvec.
// 256 threads = 8 warps; warp w owns w_hh rows [48w, 48w+48) as 3 m16-tiles.
// A-fragments (fp16 weights) live in registers for all 2048 steps (96 regs).
// Per step: h (fp16, smem) -> B fragments -> 24 x mma.m16n8k16 (fp32 acc,
// even/odd K-chain split) -> lanes tig==0 store 48 row sums -> bar ->
// gate threads (tid<128) run nonlinearities (gi register-resident, prefetch
// issued before the mma block) -> store h as fp16 -> bar.
// FMA-pipe floor was 768 cyc/step; HMMA floor is 48/SMSP * rt4 = 192 cyc.
// ---------------------------------------------------------------------------
__global__ __launch_bounds__(256, 1) void k_gru(const float* __restrict__ whh,
                                                const float* __restrict__ bhh) {
    __shared__ __align__(16) __half hbh[2][HH];
    __shared__ float ssum[GG];

    int tid  = threadIdx.x;
    int w    = tid >> 5, lane = tid & 31;
    int gid  = lane >> 2, tig = lane & 3;
    bool isgate = (tid < HH);

    // ---- load A fragments: 3 tiles x 8 ktiles x 4 regs ----
    uint32_t a[3][8][4];
    {
        const __half* Wh = g_whh16;
        #pragma unroll
        for (int t = 0; t < 3; t++) {
            int r0 = 48*w + 16*t + gid;
            #pragma unroll
            for (int k = 0; k < 8; k++) {
                int c0 = 16*k + 2*tig;
                a[t][k][0] = *(const uint32_t*)(Wh + (size_t)r0*HH + c0);
                a[t][k][1] = *(const uint32_t*)(Wh + (size_t)(r0+8)*HH + c0);
                a[t][k][2] = *(const uint32_t*)(Wh + (size_t)r0*HH + c0 + 8);
                a[t][k][3] = *(const uint32_t*)(Wh + (size_t)(r0+8)*HH + c0 + 8);
            }
        }
    }

    float bhr = 0.f, bhz = 0.f, bhn = 0.f, hj = 0.f;
    float gr = 0.f, gz = 0.f, gn = 0.f;
    if (isgate) {
        bhr = bhh[tid]; bhz = bhh[HH + tid]; bhn = bhh[2*HH + tid];
        gr = g_gi[tid]; gz = g_gi[HH + tid]; gn = g_gi[2*HH + tid];
    }
    if (isgate) { hbh[0][tid] = __float2half(0.f); hbh[1][tid] = __float2half(0.f); }
    __syncthreads();

    for (int n = 0; n < NN; n++) {
        int p = n & 1;
        // prefetch next step's gi early; latency hides under mma + barrier
        float pr = 0.f, pz = 0.f, pn_ = 0.f;
        if (isgate && n + 1 < NN) {
            const float* gp = g_gi + (size_t)(n + 1) * GG + tid;
            pr = __ldg(gp); pz = __ldg(gp + HH); pn_ = __ldg(gp + 2*HH);
        }

        // B fragments from h (half2 view), mma with even/odd K-chain split
        const uint32_t* h2u = (const uint32_t*)(&hbh[p][0]);   // 64 half2 words
        float d[3][2][4];
        #pragma unroll
        for (int t = 0; t < 3; t++)
            #pragma unroll
            for (int s = 0; s < 2; s++)
                #pragma unroll
                for (int i = 0; i < 4; i++) d[t][s][i] = 0.f;
        #pragma unroll
        for (int k = 0; k < 8; k++) {
            uint32_t b0 = h2u[8*k + tig];
            uint32_t b1 = h2u[8*k + tig + 4];
            int s = k & 1;
            #pragma unroll
            for (int t = 0; t < 3; t++)
                mma16816(d[t][s][0], d[t][s][1], d[t][s][2], d[t][s][3],
                         a[t][k][0], a[t][k][1], a[t][k][2], a[t][k][3], b0, b1);
        }
        if (tig == 0) {
            #pragma unroll
            for (int t = 0; t < 3; t++) {
                int rb = 48*w + 16*t;
                ssum[rb + gid]     = d[t][0][0] + d[t][1][0];
                ssum[rb + gid + 8] = d[t][0][2] + d[t][1][2];
            }
        }
        __syncthreads();

        if (isgate) {
            float sr = ssum[tid], sz = ssum[HH + tid], sn = ssum[2*HH + tid];
            float r  = fsig(gr + sr + bhr);
            float z  = fsig(gz + sz + bhz);
            float ta = gn + r * (sn + bhn);
            float nv = 2.0f * fsig(2.0f * ta) - 1.0f;     // tanh
            hj = (1.0f - z) * nv + z * hj;
            hbh[p ^ 1][tid] = __float2half(hj);           // critical STS first
            g_hist[(size_t)n * HH + tid] = hj;            // off critical path
            gr = pr; gz = pz; gn = pn_;
        }
        __syncthreads();
    }
}

// out[n] = hist[n,:] . fc_w + fc_b  (one warp per n)
__global__ void k_out(const float* __restrict__ fcw, const float* __restrict__ fcb,
                      float* __restrict__ out) {
    int w = threadIdx.x >> 5, lane = threadIdx.x & 31;
    int n = blockIdx.x * 8 + w;
    const float4* hp = (const float4*)(g_hist + (size_t)n*HH);
    const float4* wp = (const float4*)fcw;
    float4 h = hp[lane], ww = wp[lane];
    float s = h.x*ww.x + h.y*ww.y + h.z*ww.z + h.w*ww.w;
    s += __shfl_xor_sync(0xFFFFFFFFu, s, 16);
    s += __shfl_xor_sync(0xFFFFFFFFu, s, 8);
    s += __shfl_xor_sync(0xFFFFFFFFu, s, 4);
    s += __shfl_xor_sync(0xFFFFFFFFu, s, 2);
    s += __shfl_xor_sync(0xFFFFFFFFu, s, 1);
    if (lane == 0) out[n] = s + fcb[0];
}

// ---------------- launch ----------------
extern "C" void kernel_launch(void* const* d_in, const int* in_sizes, int n_in,
                              void* d_out, int out_size) {
    const float* x   = (const float*)d_in[0];
    const int*   ei  = (const int*)  d_in[1];
    const float* W1  = (const float*)d_in[2];
    const float* b1  = (const float*)d_in[3];
    const float* W2  = (const float*)d_in[4];
    const float* b2  = (const float*)d_in[5];
    const float* wih = (const float*)d_in[6];
    const float* whh = (const float*)d_in[7];
    const float* bih = (const float*)d_in[8];
    const float* bhh = (const float*)d_in[9];
    const float* fcw = (const float*)d_in[10];
    const float* fcb = (const float*)d_in[11];
    float* out = (float*)d_out;

    k_detect<<<1, 32>>>(ei);
    k_init<<<(NN*HH + 255)/256, 256>>>();
    k_deg<<<EE/256, 256>>>(ei);
    k_dinv<<<(NN + 255)/256, 256>>>();
    k_xs1<<<NN, HH>>>(x, W1);
    k_scat1<<<EE/4, 512>>>(ei);
    k_xs2<<<NN, HH>>>(W2, b1);
    k_scat2<<<EE/4, 512>>>(ei);
    k_wT<<<GG*HH/256, 256>>>(wih);
    k_w16<<<GG*HH/256, 256>>>(whh);
    k_gi<<<NN/16, GG>>>(bih, b2);
    k_gru<<<1, 256>>>(whh, bhh);
    k_out<<<NN/8, 256>>>(fcw, fcb, out);
}

// round 7
// speedup vs baseline: 3.3443x; 1.3470x over previous
#include <cuda_runtime.h>
#include <cuda_fp16.h>
#include <cstdint>

#define NN 2048
#define TT 128
#define FF 64
#define HH 128
#define GG 384   // 3*H
#define EE 32768

// ---------------- scratch (device globals: no allocs allowed) ----------------
__device__ float g_deg[NN];
__device__ float g_dinv[NN];
__device__ float g_xs1[NN*HH];
__device__ float g_acc1[NN*HH];
__device__ float g_xs2[NN*HH];
__device__ float g_acc2[NN*HH];
__device__ float g_wT[HH*GG];     // w_ih transposed: [k][g]
__device__ float g_gi[NN*GG];     // precomputed input gates (+b_ih)
__device__ float g_hist[NN*HH];   // h after each GRU step
__device__ __half g_whh16[GG*HH]; // w_hh rounded to fp16 (for tensor-core matvec)
__device__ int   g_stride;        // 1 if edge_index is int32, 2 if int64 words

// ---------------- helpers ----------------
__device__ __forceinline__ float ftanh(float x) {
    float y; asm("tanh.approx.f32 %0, %1;" : "=f"(y) : "f"(x)); return y;
}
__device__ __forceinline__ float fsig(float x) {          // sigmoid via MUFU.TANH
    return fmaf(0.5f, ftanh(0.5f * x), 0.5f);
}
__device__ __forceinline__ void mma16816(float& d0, float& d1, float& d2, float& d3,
                                         uint32_t a0, uint32_t a1, uint32_t a2, uint32_t a3,
                                         uint32_t b0, uint32_t b1) {
    asm volatile(
        "mma.sync.aligned.m16n8k16.row.col.f32.f16.f16.f32 "
        "{%0,%1,%2,%3}, {%4,%5,%6,%7}, {%8,%9}, {%0,%1,%2,%3};"
        : "+f"(d0), "+f"(d1), "+f"(d2), "+f"(d3)
        : "r"(a0), "r"(a1), "r"(a2), "r"(a3), "r"(b0), "r"(b1));
}

// ---------------- kernels ----------------

// Detect int32 vs int64 edge_index by inspecting high words (values < 2048, so
// int64 storage means every odd 32-bit word is zero).
__global__ void k_detect(const int* __restrict__ ei) {
    int any = 0;
    for (int i = threadIdx.x; i < 1024; i += 32) any |= ei[2*i + 1];
    unsigned b = __ballot_sync(0xFFFFFFFFu, any != 0);
    if (threadIdx.x == 0) g_stride = b ? 1 : 2;
}

__global__ void k_init() {
    int i = blockIdx.x * blockDim.x + threadIdx.x;
    if (i < NN*HH) { g_acc1[i] = 0.f; g_acc2[i] = 0.f; }
    if (i < NN)    g_deg[i] = 1.0f;   // self loop
}

__global__ void k_deg(const int* __restrict__ ei) {
    int e = blockIdx.x * blockDim.x + threadIdx.x;
    if (e < EE) {
        int s = g_stride;
        int d = ei[(EE + e) * s];
        atomicAdd(&g_deg[d], 1.0f);
    }
}

__global__ void k_dinv() {
    int n = blockIdx.x * blockDim.x + threadIdx.x;
    if (n < NN) g_dinv[n] = rsqrtf(g_deg[n]);
}

// xs1[n,:] = dinv[n] * (x[n,127,:] @ W1)
__global__ void k_xs1(const float* __restrict__ x, const float* __restrict__ W1) {
    __shared__ float xr[FF];
    int n = blockIdx.x, t = threadIdx.x;
    if (t < FF) xr[t] = x[n*(TT*FF) + 127*FF + t];
    __syncthreads();
    float a = 0.f;
    #pragma unroll
    for (int k = 0; k < FF; k++) a = fmaf(xr[k], W1[k*HH + t], a);
    g_xs1[n*HH + t] = a * g_dinv[n];
}

__global__ void k_scat1(const int* __restrict__ ei) {
    int t = threadIdx.x;
    int e = blockIdx.x * 4 + (t >> 7);
    int j = t & 127;
    int s = g_stride;
    int sr = ei[e * s], d = ei[(EE + e) * s];
    atomicAdd(&g_acc1[d*HH + j], g_xs1[sr*HH + j]);
}

// h1 row computed inline (fin1 fused); xs2[n,:] = dinv[n] * (h1[n,:] @ W2)
__global__ void k_xs2(const float* __restrict__ W2, const float* __restrict__ b1) {
    __shared__ float hr[HH];
    int n = blockIdx.x, t = threadIdx.x;
    float d = g_dinv[n];
    hr[t] = d * (g_acc1[n*HH + t] + g_xs1[n*HH + t]) + b1[t];
    __syncthreads();
    float a = 0.f;
    #pragma unroll
    for (int k = 0; k < HH; k++) a = fmaf(hr[k], W2[k*HH + t], a);
    g_xs2[n*HH + t] = a * d;
}

__global__ void k_scat2(const int* __restrict__ ei) {
    int t = threadIdx.x;
    int e = blockIdx.x * 4 + (t >> 7);
    int j = t & 127;
    int s = g_stride;
    int sr = ei[e * s], d = ei[(EE + e) * s];
    atomicAdd(&g_acc2[d*HH + j], g_xs2[sr*HH + j]);
}

// fused: w_ih transpose + w_hh fp16 conversion (same GG*HH domain)
__global__ void k_wprep(const float* __restrict__ wih, const float* __restrict__ whh) {
    int i = blockIdx.x * blockDim.x + threadIdx.x;
    if (i < GG*HH) {
        int g = i >> 7, k = i & 127;
        g_wT[k*GG + g] = wih[i];
        g_whh16[i] = __float2half_rn(whh[i]);
    }
}

// GI[n,g] = h2[n,:] . w_ih[g,:] + b_ih[g]   (16 rows per block; h2 computed
// inline from acc2/xs2 — fin2 fused)
__global__ void k_gi(const float* __restrict__ bih, const float* __restrict__ b2) {
    __shared__ float hs[16][HH];
    int g = threadIdx.x;
    int n0 = blockIdx.x * 16;
    for (int i = g; i < 16*HH; i += GG) {
        int r = i >> 7, k = i & 127;
        hs[r][k] = g_dinv[n0 + r] * (g_acc2[n0*HH + i] + g_xs2[n0*HH + i]) + b2[k];
    }
    __syncthreads();
    float acc[16];
    #pragma unroll
    for (int i = 0; i < 16; i++) acc[i] = 0.f;
    for (int k = 0; k < HH; k++) {
        float w = g_wT[k*GG + g];
        #pragma unroll
        for (int i = 0; i < 16; i++) acc[i] = fmaf(hs[i][k], w, acc[i]);
    }
    float b = bih[g];
    #pragma unroll
    for (int i = 0; i < 16; i++) g_gi[(n0 + i)*GG + g] = acc[i] + b;
}

// ---------------------------------------------------------------------------
// Sequential GRU on ONE SM using the tensor core for the recurrent matvec.
// 256 threads = 8 warps; warp w owns w_hh rows [48w, 48w+48) as 3 m16-tiles.
// A-fragments (fp16 weights) live in registers for all 2048 steps (96 regs).
// Per step: h (fp16, smem) -> B fragments -> 24 x mma.m16n8k16 (fp32 acc,
// even/odd K-chain split) -> lanes tig==0 store 48 row sums -> bar ->
// gate threads (tid<128) run MUFU.TANH-based nonlinearities (gi register-
// resident, biases pre-added off the critical path) -> store h fp16 -> bar.
// ---------------------------------------------------------------------------
__global__ __launch_bounds__(256, 1) void k_gru(const float* __restrict__ whh,
                                                const float* __restrict__ bhh) {
    __shared__ __align__(16) __half hbh[2][HH];
    __shared__ float ssum[GG];

    int tid  = threadIdx.x;
    int w    = tid >> 5, lane = tid & 31;
    int gid  = lane >> 2, tig = lane & 3;
    bool isgate = (tid < HH);

    // ---- load A fragments: 3 tiles x 8 ktiles x 4 regs ----
    uint32_t a[3][8][4];
    {
        const __half* Wh = g_whh16;
        #pragma unroll
        for (int t = 0; t < 3; t++) {
            int r0 = 48*w + 16*t + gid;
            #pragma unroll
            for (int k = 0; k < 8; k++) {
                int c0 = 16*k + 2*tig;
                a[t][k][0] = *(const uint32_t*)(Wh + (size_t)r0*HH + c0);
                a[t][k][1] = *(const uint32_t*)(Wh + (size_t)(r0+8)*HH + c0);
                a[t][k][2] = *(const uint32_t*)(Wh + (size_t)r0*HH + c0 + 8);
                a[t][k][3] = *(const uint32_t*)(Wh + (size_t)(r0+8)*HH + c0 + 8);
            }
        }
    }

    // gate-thread state: biases pre-added into the gi values (off critical path)
    float bhr = 0.f, bhz = 0.f, bhn = 0.f, hj = 0.f;
    float grb = 0.f, gzb = 0.f, gn = 0.f;
    if (isgate) {
        bhr = bhh[tid]; bhz = bhh[HH + tid]; bhn = bhh[2*HH + tid];
        grb = g_gi[tid] + bhr;
        gzb = g_gi[HH + tid] + bhz;
        gn  = g_gi[2*HH + tid];
    }
    if (isgate) { hbh[0][tid] = __float2half(0.f); hbh[1][tid] = __float2half(0.f); }
    __syncthreads();

    for (int n = 0; n < NN; n++) {
        int p = n & 1;
        // prefetch next step's gi early; latency hides under mma + barrier
        float pr = 0.f, pz = 0.f, pn_ = 0.f;
        if (isgate && n + 1 < NN) {
            const float* gp = g_gi + (size_t)(n + 1) * GG + tid;
            pr = __ldg(gp); pz = __ldg(gp + HH); pn_ = __ldg(gp + 2*HH);
        }

        // B fragments from h (half2 view), mma with even/odd K-chain split
        const uint32_t* h2u = (const uint32_t*)(&hbh[p][0]);   // 64 half2 words
        float d[3][2][4];
        #pragma unroll
        for (int t = 0; t < 3; t++)
            #pragma unroll
            for (int s = 0; s < 2; s++)
                #pragma unroll
                for (int i = 0; i < 4; i++) d[t][s][i] = 0.f;
        #pragma unroll
        for (int k = 0; k < 8; k++) {
            uint32_t b0 = h2u[8*k + tig];
            uint32_t b1 = h2u[8*k + tig + 4];
            int s = k & 1;
            #pragma unroll
            for (int t = 0; t < 3; t++)
                mma16816(d[t][s][0], d[t][s][1], d[t][s][2], d[t][s][3],
                         a[t][k][0], a[t][k][1], a[t][k][2], a[t][k][3], b0, b1);
        }
        if (tig == 0) {
            #pragma unroll
            for (int t = 0; t < 3; t++) {
                int rb = 48*w + 16*t;
                ssum[rb + gid]     = d[t][0][0] + d[t][1][0];
                ssum[rb + gid + 8] = d[t][0][2] + d[t][1][2];
            }
        }
        __syncthreads();

        if (isgate) {
            float sr = ssum[tid], sz = ssum[HH + tid], sn = ssum[2*HH + tid];
            float r  = fsig(grb + sr);                    // MUFU.TANH sigmoid
            float z  = fsig(gzb + sz);
            float nv = ftanh(gn + r * (sn + bhn));        // MUFU.TANH
            hj = fmaf(z, hj - nv, nv);                    // (1-z)n + z h
            hbh[p ^ 1][tid] = __float2half(hj);           // critical STS first
            g_hist[(size_t)n * HH + tid] = hj;            // off critical path
            grb = pr + bhr; gzb = pz + bhz; gn = pn_;
        }
        __syncthreads();
    }
}

// out[n] = hist[n,:] . fc_w + fc_b  (one warp per n)
__global__ void k_out(const float* __restrict__ fcw, const float* __restrict__ fcb,
                      float* __restrict__ out) {
    int w = threadIdx.x >> 5, lane = threadIdx.x & 31;
    int n = blockIdx.x * 8 + w;
    const float4* hp = (const float4*)(g_hist + (size_t)n*HH);
    const float4* wp = (const float4*)fcw;
    float4 h = hp[lane], ww = wp[lane];
    float s = h.x*ww.x + h.y*ww.y + h.z*ww.z + h.w*ww.w;
    s += __shfl_xor_sync(0xFFFFFFFFu, s, 16);
    s += __shfl_xor_sync(0xFFFFFFFFu, s, 8);
    s += __shfl_xor_sync(0xFFFFFFFFu, s, 4);
    s += __shfl_xor_sync(0xFFFFFFFFu, s, 2);
    s += __shfl_xor_sync(0xFFFFFFFFu, s, 1);
    if (lane == 0) out[n] = s + fcb[0];
}

// ---------------- launch ----------------
extern "C" void kernel_launch(void* const* d_in, const int* in_sizes, int n_in,
                              void* d_out, int out_size) {
    const float* x   = (const float*)d_in[0];
    const int*   ei  = (const int*)  d_in[1];
    const float* W1  = (const float*)d_in[2];
    const float* b1  = (const float*)d_in[3];
    const float* W2  = (const float*)d_in[4];
    const float* b2  = (const float*)d_in[5];
    const float* wih = (const float*)d_in[6];
    const float* whh = (const float*)d_in[7];
    const float* bih = (const float*)d_in[8];
    const float* bhh = (const float*)d_in[9];
    const float* fcw = (const float*)d_in[10];
    const float* fcb = (const float*)d_in[11];
    float* out = (float*)d_out;

    k_detect<<<1, 32>>>(ei);
    k_init<<<(NN*HH + 255)/256, 256>>>();
    k_deg<<<EE/256, 256>>>(ei);
    k_dinv<<<(NN + 255)/256, 256>>>();
    k_xs1<<<NN, HH>>>(x, W1);
    k_scat1<<<EE/4, 512>>>(ei);
    k_xs2<<<NN, HH>>>(W2, b1);
    k_scat2<<<EE/4, 512>>>(ei);
    k_wprep<<<GG*HH/256, 256>>>(wih, whh);
    k_gi<<<NN/16, GG>>>(bih, b2);
    k_gru<<<1, 256>>>(whh, bhh);
    k_out<<<NN/8, 256>>>(fcw, fcb, out);
}